// round 8
// baseline (speedup 1.0000x reference)
#include <cuda_runtime.h>
#include <cstdint>

#define DV 16
#define HV 64
#define WV 64
#define NVOX (DV*HV*WV)   /* 65536 voxels */
#define JP   64           /* padded channel count (>= J=55) */

// Scratch (no allocations allowed)
__device__ __align__(16) float g_vol_t[NVOX * JP];     // 16 MB: [voxel][JP]
__device__ int g_mask_is_u8;                           // runtime mask-dtype flag

// ---------------------------------------------------------------------------
// mask dtype detection: int32 0/1 has zero bytes at offsets %4!=0; u8 doesn't.
// ---------------------------------------------------------------------------
__global__ void reset_flag_kernel() { g_mask_is_u8 = 0; }

__global__ void detect_mask_kernel(const unsigned char* __restrict__ m, int N) {
    int i = blockIdx.x * 256 + threadIdx.x;
    int limit = N < 65536 ? N : 65536;
    if (i < limit && (i & 3) != 0 && m[i] != 0)
        atomicOr(&g_mask_is_u8, 1);
}

// ---------------------------------------------------------------------------
// Kernel 1: vol [J][D][H][W] -> g_vol_t [D*H*W][JP] (channel-contiguous, padded)
// ---------------------------------------------------------------------------
__global__ void __launch_bounds__(256) transpose_vol_kernel(const float* __restrict__ vol, int J) {
    __shared__ float tile[64][65];
    int v0 = blockIdx.x * 64;
    #pragma unroll
    for (int e = threadIdx.x; e < 64 * 64; e += 256) {
        int j = e >> 6, vi = e & 63;
        tile[j][vi] = (j < J) ? vol[j * NVOX + v0 + vi] : 0.0f;
    }
    __syncthreads();
    #pragma unroll
    for (int e = threadIdx.x; e < 64 * 64; e += 256) {
        int vi = e >> 6, j = e & 63;
        g_vol_t[(v0 + vi) * JP + j] = tile[j][vi];
    }
}

// ---------------------------------------------------------------------------
// packed f32x2 helpers
// ---------------------------------------------------------------------------
static __device__ __forceinline__ unsigned long long ffma2(
    unsigned long long a, unsigned long long b, unsigned long long c) {
    unsigned long long d;
    asm("fma.rn.f32x2 %0, %1, %2, %3;" : "=l"(d) : "l"(a), "l"(b), "l"(c));
    return d;
}
static __device__ __forceinline__ unsigned long long splat2(float w) {
    unsigned long long d;
    asm("mov.b64 %0, {%1, %1};" : "=l"(d) : "f"(w));
    return d;
}
static __device__ __forceinline__ float2 u2f2(unsigned long long v) {
    float2 r;
    asm("mov.b64 {%0, %1}, %2;" : "=f"(r.x), "=f"(r.y) : "l"(v));
    return r;
}
static __device__ __forceinline__ float4 fma4(float a, float4 b, float4 c) {
    float4 r;
    r.x = fmaf(a, b.x, c.x); r.y = fmaf(a, b.y, c.y);
    r.z = fmaf(a, b.z, c.z); r.w = fmaf(a, b.w, c.w);
    return r;
}

#define NWRP 4
#define PPW  16   /* points per warp (2 lanes per point) */

// ---------------------------------------------------------------------------
// Kernel 2: fused deformer. 128 threads = 4 warps; each warp owns 16 points,
// each point is served by a LANE PAIR (even lane: tfs_inv matrix A,
// odd lane: tfs matrix C). Phase 1 stages 55 weights per point into s_ws
// (cooperative gather / coalesced lbsw). Phase 2: packed-f32x2 blend with
// 16 accumulator registers per thread. Epilogue exchanges A/C via smem.
// ---------------------------------------------------------------------------
__global__ void __launch_bounds__(128, 6) deform_kernel(
    const float* __restrict__ xc, const float* __restrict__ shape_off,
    const float* __restrict__ pose_off, const float* __restrict__ tfs,
    const float* __restrict__ tfs_inv, const float* __restrict__ poseoff_ori,
    const void* __restrict__ mask_raw, const float* __restrict__ lbsw,
    const float* __restrict__ offk, const float* __restrict__ sclk,
    float* __restrict__ out_xd, float* __restrict__ out_w,
    int N, int J)
{
    const int b = blockIdx.y;
    __shared__ float4 s_ti[56 * 4 + 1];        // tfs_inv rows (+1 f4: bank-offset s_tf)
    __shared__ float4 s_tf[56 * 4];            // tfs[b] rows
    __shared__ float4 s_ws[NWRP][14][17];      // staged weights [warp][chunk][pt]
    __shared__ int    s_po[NWRP][PPW][9];      // staged corner offsets (pad 9)
    __shared__ float  s_pw[NWRP][PPW][9];      // staged corner weights (pad 9)

    {
        float* sti = (float*)s_ti;
        float* stf = (float*)s_tf;
        for (int e = threadIdx.x; e < 56 * 16; e += 128) {
            int j = e >> 4, k = e & 15;
            sti[e] = (j < J) ? tfs_inv[j * 16 + k] : 0.0f;
            stf[e] = (j < J) ? tfs[(b * J + j) * 16 + k] : 0.0f;
        }
    }
    __syncthreads();

    const int warp = threadIdx.x >> 5;
    const int lane = threadIdx.x & 31;
    const int pp     = lane >> 1;              // point within warp (0..15)
    const int matsel = lane & 1;               // 0: A (tfs_inv), 1: C (tfs)
    const int wbase = (blockIdx.x * NWRP + warp) * PPW;
    const int n  = wbase + pp;
    const int nc = n < N ? n : N - 1;          // clamp; no early return (warp ops!)
    const long idx = (long)b * N + nc;

    // ----- per-point setup (computed redundantly by the lane pair) -----
    bool msk;
    if (g_mask_is_u8) msk = (((const unsigned char*)mask_raw)[nc] != 0);
    else              msk = (((const int*)mask_raw)[nc] != 0);
    const unsigned mbits = __ballot_sync(0xffffffffu, msk);  // bit 2p == bit 2p+1

    const float px = xc[idx * 3 + 0], py = xc[idx * 3 + 1], pz = xc[idx * 3 + 2];
    const float fx = (px + offk[0]) * sclk[0];
    const float fy = (py + offk[1]) * sclk[1];
    const float fz = (pz + offk[2]) * sclk[2];

    float ixf = fminf(fmaxf((fx + 1.0f) * 0.5f * (float)(WV - 1), 0.0f), (float)(WV - 1));
    float iyf = fminf(fmaxf((fy + 1.0f) * 0.5f * (float)(HV - 1), 0.0f), (float)(HV - 1));
    float izf = fminf(fmaxf((fz + 1.0f) * 0.5f * (float)(DV - 1), 0.0f), (float)(DV - 1));
    float xf = floorf(ixf), yf = floorf(iyf), zf = floorf(izf);
    float wx = ixf - xf, wy = iyf - yf, wz = izf - zf;
    int x0 = (int)xf, y0 = (int)yf, z0 = (int)zf;
    int x1 = min(x0 + 1, WV - 1), y1 = min(y0 + 1, HV - 1), z1 = min(z0 + 1, DV - 1);

    int r00 = (z0 * HV + y0) * WV, r01 = (z0 * HV + y1) * WV;
    int r10 = (z1 * HV + y0) * WV, r11 = (z1 * HV + y1) * WV;
    float mx = 1.0f - wx, my = 1.0f - wy, mz = 1.0f - wz;

    if (matsel == 0) {   // even lane stages corner data for its point
        int*   po = s_po[warp][pp];
        float* pw = s_pw[warp][pp];
        po[0] = (r00 + x0) * 16;  pw[0] = mz * my * mx;
        po[1] = (r00 + x1) * 16;  pw[1] = mz * my * wx;
        po[2] = (r01 + x0) * 16;  pw[2] = mz * wy * mx;
        po[3] = (r01 + x1) * 16;  pw[3] = mz * wy * wx;
        po[4] = (r10 + x0) * 16;  pw[4] = wz * my * mx;
        po[5] = (r10 + x1) * 16;  pw[5] = wz * my * wx;
        po[6] = (r11 + x0) * 16;  pw[6] = wz * wy * mx;
        po[7] = (r11 + x1) * 16;  pw[7] = wz * wy * wx;
    }
    __syncwarp();

    // ----- phase 1: stage all 16 points' weights into s_ws -----
    const float4* vt4 = (const float4*)g_vol_t;
    float* wsf = (float*)s_ws[warp];            // scalar view: ((j>>2)*17+p)*4+(j&3)
    const int c = lane & 15;
    const int half = lane >> 4;                 // 0: corners {0,2,4,6}, 1: {1,3,5,7}
    const int j1 = lane, j2 = lane + 32;        // scalar lanes for masked rows
    const int i1 = ((j1 >> 2) * 17) * 4 + (j1 & 3);
    const int i2 = ((j2 >> 2) * 17) * 4 + (j2 & 3);

    #pragma unroll 2
    for (int p = 0; p < PPW; ++p) {
        if ((mbits >> (2 * p)) & 1u) {
            // masked: coalesced scalar load of lbsw row (220 B, 4B-aligned)
            int np = wbase + p;
            if (np >= N) continue;
            const float* row = lbsw + (long)np * J;
            wsf[i1 + p * 4] = row[j1];
            if (j2 < 56)
                wsf[i2 + p * 4] = (j2 < J) ? row[j2] : 0.0f;
        } else {
            // unmasked: cooperative trilinear gather
            const int*   po = s_po[warp][p];    // broadcast reads
            const float* pw = s_pw[warp][p];
            float4 acc = make_float4(0.f, 0.f, 0.f, 0.f);
            float4 v;
            v = vt4[po[half + 0] + c]; acc = fma4(pw[half + 0], v, acc);
            v = vt4[po[half + 2] + c]; acc = fma4(pw[half + 2], v, acc);
            v = vt4[po[half + 4] + c]; acc = fma4(pw[half + 4], v, acc);
            v = vt4[po[half + 6] + c]; acc = fma4(pw[half + 6], v, acc);
            acc.x += __shfl_xor_sync(0xffffffffu, acc.x, 16);
            acc.y += __shfl_xor_sync(0xffffffffu, acc.y, 16);
            acc.z += __shfl_xor_sync(0xffffffffu, acc.z, 16);
            acc.w += __shfl_xor_sync(0xffffffffu, acc.w, 16);
            if (half == 0 && c < 14) s_ws[warp][c][p] = acc;
        }
    }
    __syncwarp();

    // ----- phase 2: lane-pair packed-f32x2 blend (own matrix only) -----
    const float4* tb = matsel ? s_tf : s_ti;
    unsigned long long Acc[8];
    #pragma unroll
    for (int i = 0; i < 8; ++i) Acc[i] = 0ull;

    #pragma unroll
    for (int cc = 0; cc < 14; ++cc) {
        float4 w4 = s_ws[warp][cc][pp];
        #pragma unroll
        for (int jj = 0; jj < 4; ++jj) {
            float f = jj == 0 ? w4.x : jj == 1 ? w4.y : jj == 2 ? w4.z : w4.w;
            unsigned long long s = splat2(f);
            const ulonglong2* rp = (const ulonglong2*)&tb[(cc * 4 + jj) * 4];
            ulonglong2 r0 = rp[0], r1 = rp[1], r2 = rp[2], r3 = rp[3];
            Acc[0] = ffma2(s, r0.x, Acc[0]); Acc[1] = ffma2(s, r0.y, Acc[1]);
            Acc[2] = ffma2(s, r1.x, Acc[2]); Acc[3] = ffma2(s, r1.y, Acc[3]);
            Acc[4] = ffma2(s, r2.x, Acc[4]); Acc[5] = ffma2(s, r2.y, Acc[5]);
            Acc[6] = ffma2(s, r3.x, Acc[6]); Acc[7] = ffma2(s, r3.y, Acc[7]);
        }
    }

    // own matrix rows as float4
    float2 m0l = u2f2(Acc[0]), m0h = u2f2(Acc[1]);
    float2 m1l = u2f2(Acc[2]), m1h = u2f2(Acc[3]);
    float2 m2l = u2f2(Acc[4]), m2h = u2f2(Acc[5]);
    float2 m3l = u2f2(Acc[6]), m3h = u2f2(Acc[7]);
    float4 M0 = {m0l.x, m0l.y, m0h.x, m0h.y};
    float4 M1 = {m1l.x, m1l.y, m1h.x, m1h.y};
    float4 M2 = {m2l.x, m2l.y, m2h.x, m2h.y};
    float4 M3 = {m3l.x, m3l.y, m3h.x, m3h.y};

    // ----- epilogue: exchange matrices within the lane pair via smem -----
    __syncwarp();
    float4* scr = (float4*)s_ws[warp];          // reuse (done reading weights)
    scr[0 * 33 + lane] = M0;  scr[1 * 33 + lane] = M1;
    scr[2 * 33 + lane] = M2;  scr[3 * 33 + lane] = M3;
    __syncwarp();
    const int partner = lane ^ 1;
    float4 P0 = scr[0 * 33 + partner], P1 = scr[1 * 33 + partner];
    float4 P2 = scr[2 * 33 + partner], P3 = scr[3 * 33 + partner];

    float4 A0 = matsel ? P0 : M0, A1 = matsel ? P1 : M1;
    float4 A2 = matsel ? P2 : M2, A3 = matsel ? P3 : M3;
    float4 C0 = matsel ? M0 : P0, C1 = matsel ? M1 : P1;
    float4 C2 = matsel ? M2 : P2, C3 = matsel ? M3 : P3;

    if (n < N) {
        float4* ow = ((float4*)out_w) + idx * 4;
        if (matsel == 0) {
            // xd
            float cx = A0.x * px + A0.y * py + A0.z * pz + A0.w;
            float cy = A1.x * px + A1.y * py + A1.z * pz + A1.w;
            float cz = A2.x * px + A2.y * py + A2.z * pz + A2.w;
            const long n3 = (long)nc * 3, i3 = idx * 3;
            float sx = cx - poseoff_ori[n3 + 0] + shape_off[i3 + 0] + pose_off[i3 + 0];
            float sy = cy - poseoff_ori[n3 + 1] + shape_off[i3 + 1] + pose_off[i3 + 1];
            float sz = cz - poseoff_ori[n3 + 2] + shape_off[i3 + 2] + pose_off[i3 + 2];
            out_xd[i3 + 0] = C0.x * sx + C0.y * sy + C0.z * sz + C0.w;
            out_xd[i3 + 1] = C1.x * sx + C1.y * sy + C1.z * sz + C1.w;
            out_xd[i3 + 2] = C2.x * sx + C2.y * sy + C2.z * sz + C2.w;
            // R rows 0, 1
            float4 R;
            R.x = C0.x*A0.x + C0.y*A1.x + C0.z*A2.x + C0.w*A3.x;
            R.y = C0.x*A0.y + C0.y*A1.y + C0.z*A2.y + C0.w*A3.y;
            R.z = C0.x*A0.z + C0.y*A1.z + C0.z*A2.z + C0.w*A3.z;
            R.w = C0.x*A0.w + C0.y*A1.w + C0.z*A2.w + C0.w*A3.w;
            ow[0] = R;
            R.x = C1.x*A0.x + C1.y*A1.x + C1.z*A2.x + C1.w*A3.x;
            R.y = C1.x*A0.y + C1.y*A1.y + C1.z*A2.y + C1.w*A3.y;
            R.z = C1.x*A0.z + C1.y*A1.z + C1.z*A2.z + C1.w*A3.z;
            R.w = C1.x*A0.w + C1.y*A1.w + C1.z*A2.w + C1.w*A3.w;
            ow[1] = R;
        } else {
            // R rows 2, 3
            float4 R;
            R.x = C2.x*A0.x + C2.y*A1.x + C2.z*A2.x + C2.w*A3.x;
            R.y = C2.x*A0.y + C2.y*A1.y + C2.z*A2.y + C2.w*A3.y;
            R.z = C2.x*A0.z + C2.y*A1.z + C2.z*A2.z + C2.w*A3.z;
            R.w = C2.x*A0.w + C2.y*A1.w + C2.z*A2.w + C2.w*A3.w;
            ow[2] = R;
            R.x = C3.x*A0.x + C3.y*A1.x + C3.z*A2.x + C3.w*A3.x;
            R.y = C3.x*A0.y + C3.y*A1.y + C3.z*A2.y + C3.w*A3.y;
            R.z = C3.x*A0.z + C3.y*A1.z + C3.z*A2.z + C3.w*A3.z;
            R.w = C3.x*A0.w + C3.y*A1.w + C3.z*A2.w + C3.w*A3.w;
            ow[3] = R;
        }
    }
}

// ---------------------------------------------------------------------------
// Host: resolve inputs by exact element count (ordering-independent binding).
// ---------------------------------------------------------------------------
extern "C" void kernel_launch(void* const* d_in, const int* in_sizes, int n_in,
                              void* d_out, int out_size) {
    const float *tfs = nullptr, *tfs_inv = nullptr, *poseoff_ori = nullptr,
                *lbsw = nullptr, *vol = nullptr;
    const void  *mask = nullptr;
    const float *p3M[3] = {nullptr, nullptr, nullptr};
    const float *psm[2] = {nullptr, nullptr};
    int c3 = 0, cs = 0;
    int idx_mask = -1, idx_first3M = -1;

    for (int i = 0; i < n_in; i++) {
        switch (in_sizes[i]) {
            case 3520:     tfs = (const float*)d_in[i]; break;
            case 880:      tfs_inv = (const float*)d_in[i]; break;
            case 750000:   poseoff_ori = (const float*)d_in[i]; break;
            case 13750000: lbsw = (const float*)d_in[i]; break;
            case 250000:   mask = d_in[i]; idx_mask = i; break;
            case 3604480:  vol = (const float*)d_in[i]; break;
            case 3:        if (cs < 2) psm[cs++] = (const float*)d_in[i]; break;
            case 3000000:
                if (c3 == 0) idx_first3M = i;
                if (c3 < 3) p3M[c3++] = (const float*)d_in[i];
                break;
            default: break;
        }
    }

    const int J = 55, N = 250000, B = 4;

    const float* xc        = (idx_mask >= 0 && idx_first3M >= 0 && idx_mask < idx_first3M)
                             ? p3M[2] : p3M[0];
    const float* shape_off = (xc == p3M[0]) ? p3M[1] : p3M[0];
    const float* pose_off  = (xc == p3M[0]) ? p3M[2] : p3M[1];
    const float* offk = psm[0];
    const float* sclk = psm[1];

    float* out_xd = (float*)d_out;
    float* out_w  = out_xd + (size_t)B * N * 3;

    reset_flag_kernel<<<1, 1>>>();
    detect_mask_kernel<<<(65536 + 255) / 256, 256>>>((const unsigned char*)mask, N);
    transpose_vol_kernel<<<NVOX / 64, 256>>>(vol, J);

    dim3 grid((N + 63) / 64, B);
    deform_kernel<<<grid, 128>>>(xc, shape_off, pose_off, tfs, tfs_inv,
                                 poseoff_ori, mask, lbsw, offk, sclk,
                                 out_xd, out_w, N, J);
}

// round 9
// speedup vs baseline: 1.2337x; 1.2337x over previous
#include <cuda_runtime.h>
#include <cstdint>

#define DV 16
#define HV 64
#define WV 64
#define NVOX (DV*HV*WV)   /* 65536 voxels */
#define JP   64           /* padded channel count (>= J=55) */

// Scratch (no allocations allowed)
__device__ __align__(16) float g_vol_t[NVOX * JP];     // 16 MB: [voxel][JP]
__device__ int g_mask_is_u8;                           // runtime mask-dtype flag

// ---------------------------------------------------------------------------
// mask dtype detection: int32 0/1 has zero bytes at offsets %4!=0; u8 doesn't.
// ---------------------------------------------------------------------------
__global__ void reset_flag_kernel() { g_mask_is_u8 = 0; }

__global__ void detect_mask_kernel(const unsigned char* __restrict__ m, int N) {
    int i = blockIdx.x * 256 + threadIdx.x;
    int limit = N < 65536 ? N : 65536;
    if (i < limit && (i & 3) != 0 && m[i] != 0)
        atomicOr(&g_mask_is_u8, 1);
}

// ---------------------------------------------------------------------------
// Kernel 1: vol [J][D][H][W] -> g_vol_t [D*H*W][JP] (channel-contiguous, padded)
// ---------------------------------------------------------------------------
__global__ void __launch_bounds__(256) transpose_vol_kernel(const float* __restrict__ vol, int J) {
    __shared__ float tile[64][65];
    int v0 = blockIdx.x * 64;
    #pragma unroll
    for (int e = threadIdx.x; e < 64 * 64; e += 256) {
        int j = e >> 6, vi = e & 63;
        tile[j][vi] = (j < J) ? vol[j * NVOX + v0 + vi] : 0.0f;
    }
    __syncthreads();
    #pragma unroll
    for (int e = threadIdx.x; e < 64 * 64; e += 256) {
        int vi = e >> 6, j = e & 63;
        g_vol_t[(v0 + vi) * JP + j] = tile[j][vi];
    }
}

// ---------------------------------------------------------------------------
// packed f32x2 helpers
// ---------------------------------------------------------------------------
static __device__ __forceinline__ unsigned long long ffma2(
    unsigned long long a, unsigned long long b, unsigned long long c) {
    unsigned long long d;
    asm("fma.rn.f32x2 %0, %1, %2, %3;" : "=l"(d) : "l"(a), "l"(b), "l"(c));
    return d;
}
static __device__ __forceinline__ unsigned long long splat2(float w) {
    unsigned long long d;
    asm("mov.b64 %0, {%1, %1};" : "=l"(d) : "f"(w));
    return d;
}
static __device__ __forceinline__ float2 u2f2(unsigned long long v) {
    float2 r;
    asm("mov.b64 {%0, %1}, %2;" : "=f"(r.x), "=f"(r.y) : "l"(v));
    return r;
}
static __device__ __forceinline__ float4 fma4(float a, float4 b, float4 c) {
    float4 r;
    r.x = fmaf(a, b.x, c.x); r.y = fmaf(a, b.y, c.y);
    r.z = fmaf(a, b.z, c.z); r.w = fmaf(a, b.w, c.w);
    return r;
}

// Accumulate weight WW times tfs_inv / tfs row-block (T = j*4 in float4 units)
#define ACCW(WW, T) do {                                                       \
    unsigned long long w2 = splat2(WW);                                        \
    ulonglong2 ti0 = *(const ulonglong2*)&s_ti[(T)+0];                         \
    ulonglong2 ti1 = *(const ulonglong2*)&s_ti[(T)+1];                         \
    ulonglong2 ti2 = *(const ulonglong2*)&s_ti[(T)+2];                         \
    ulonglong2 ti3 = *(const ulonglong2*)&s_ti[(T)+3];                         \
    A[0]=ffma2(w2,ti0.x,A[0]); A[1]=ffma2(w2,ti0.y,A[1]);                      \
    A[2]=ffma2(w2,ti1.x,A[2]); A[3]=ffma2(w2,ti1.y,A[3]);                      \
    A[4]=ffma2(w2,ti2.x,A[4]); A[5]=ffma2(w2,ti2.y,A[5]);                      \
    A[6]=ffma2(w2,ti3.x,A[6]); A[7]=ffma2(w2,ti3.y,A[7]);                      \
    ulonglong2 tf0 = *(const ulonglong2*)&s_tf[(T)+0];                         \
    ulonglong2 tf1 = *(const ulonglong2*)&s_tf[(T)+1];                         \
    ulonglong2 tf2 = *(const ulonglong2*)&s_tf[(T)+2];                         \
    ulonglong2 tf3 = *(const ulonglong2*)&s_tf[(T)+3];                         \
    C[0]=ffma2(w2,tf0.x,C[0]); C[1]=ffma2(w2,tf0.y,C[1]);                      \
    C[2]=ffma2(w2,tf1.x,C[2]); C[3]=ffma2(w2,tf1.y,C[3]);                      \
    C[4]=ffma2(w2,tf2.x,C[4]); C[5]=ffma2(w2,tf2.y,C[5]);                      \
    C[6]=ffma2(w2,tf3.x,C[6]); C[7]=ffma2(w2,tf3.y,C[7]); } while(0)

#define NWRP 4

// ---------------------------------------------------------------------------
// Kernel 2: fused deformer (R5 structure; occupancy-tuned).
// 128 threads = 4 warps; each warp owns 32 points.
// Phase 1:  stage 55 weights per point into s_ws (cooperative gather / lbsw).
// Phase 2:  per-thread packed-f32x2 blend; tfs rows are warp-broadcast LDS.128.
// ---------------------------------------------------------------------------
__global__ void __launch_bounds__(128, 5) deform_kernel(
    const float* __restrict__ xc, const float* __restrict__ shape_off,
    const float* __restrict__ pose_off, const float* __restrict__ tfs,
    const float* __restrict__ tfs_inv, const float* __restrict__ poseoff_ori,
    const void* __restrict__ mask_raw, const float* __restrict__ lbsw,
    const float* __restrict__ offk, const float* __restrict__ sclk,
    float* __restrict__ out_xd, float* __restrict__ out_w,
    int N, int J)
{
    const int b = blockIdx.y;
    __shared__ float4 s_ti[56 * 4];            // tfs_inv rows (row j=55 zeroed)
    __shared__ float4 s_tf[56 * 4];            // tfs[b] rows
    __shared__ float4 s_ws[NWRP][14][33];      // staged weights [warp][chunk][pt]
    __shared__ int    s_po[NWRP][8][32];       // corner offsets [warp][corner][pt]
    __shared__ float  s_pw[NWRP][8][32];       // corner weights [warp][corner][pt]

    {
        float* sti = (float*)s_ti;
        float* stf = (float*)s_tf;
        for (int e = threadIdx.x; e < 56 * 16; e += 128) {
            int j = e >> 4, k = e & 15;
            sti[e] = (j < J) ? tfs_inv[j * 16 + k] : 0.0f;
            stf[e] = (j < J) ? tfs[(b * J + j) * 16 + k] : 0.0f;
        }
    }
    __syncthreads();

    const int warp = threadIdx.x >> 5;
    const int lane = threadIdx.x & 31;
    const int wbase = (blockIdx.x * NWRP + warp) * 32;
    const int n  = wbase + lane;
    const int nc = n < N ? n : N - 1;          // clamp; no early return (warp ops!)
    const long idx = (long)b * N + nc;

    // ----- per-point setup: mask + corner offsets/weights -----
    bool msk;
    if (g_mask_is_u8) msk = (((const unsigned char*)mask_raw)[nc] != 0);
    else              msk = (((const int*)mask_raw)[nc] != 0);
    const unsigned mbits = __ballot_sync(0xffffffffu, msk);

    const float px = xc[idx * 3 + 0], py = xc[idx * 3 + 1], pz = xc[idx * 3 + 2];
    const float fx = (px + offk[0]) * sclk[0];
    const float fy = (py + offk[1]) * sclk[1];
    const float fz = (pz + offk[2]) * sclk[2];

    float ixf = fminf(fmaxf((fx + 1.0f) * 0.5f * (float)(WV - 1), 0.0f), (float)(WV - 1));
    float iyf = fminf(fmaxf((fy + 1.0f) * 0.5f * (float)(HV - 1), 0.0f), (float)(HV - 1));
    float izf = fminf(fmaxf((fz + 1.0f) * 0.5f * (float)(DV - 1), 0.0f), (float)(DV - 1));
    float xf = floorf(ixf), yf = floorf(iyf), zf = floorf(izf);
    float wx = ixf - xf, wy = iyf - yf, wz = izf - zf;
    int x0 = (int)xf, y0 = (int)yf, z0 = (int)zf;
    int x1 = min(x0 + 1, WV - 1), y1 = min(y0 + 1, HV - 1), z1 = min(z0 + 1, DV - 1);

    int r00 = (z0 * HV + y0) * WV, r01 = (z0 * HV + y1) * WV;
    int r10 = (z1 * HV + y0) * WV, r11 = (z1 * HV + y1) * WV;
    float mx = 1.0f - wx, my = 1.0f - wy, mz = 1.0f - wz;

    {   // stage raw corner data, transposed: [corner][lane] (conflict-free STS)
        s_po[warp][0][lane] = (r00 + x0) * 16;  s_pw[warp][0][lane] = mz * my * mx;
        s_po[warp][1][lane] = (r00 + x1) * 16;  s_pw[warp][1][lane] = mz * my * wx;
        s_po[warp][2][lane] = (r01 + x0) * 16;  s_pw[warp][2][lane] = mz * wy * mx;
        s_po[warp][3][lane] = (r01 + x1) * 16;  s_pw[warp][3][lane] = mz * wy * wx;
        s_po[warp][4][lane] = (r10 + x0) * 16;  s_pw[warp][4][lane] = wz * my * mx;
        s_po[warp][5][lane] = (r10 + x1) * 16;  s_pw[warp][5][lane] = wz * my * wx;
        s_po[warp][6][lane] = (r11 + x0) * 16;  s_pw[warp][6][lane] = wz * wy * mx;
        s_po[warp][7][lane] = (r11 + x1) * 16;  s_pw[warp][7][lane] = wz * wy * wx;
    }
    __syncwarp();

    // ----- phase 1: stage all 32 points' weights into s_ws -----
    const float4* vt4 = (const float4*)g_vol_t;
    float* wsf = (float*)s_ws[warp];            // scalar view: ((j>>2)*33+p)*4+(j&3)
    const int c = lane & 15;
    const int half = lane >> 4;                 // 0: corners {0,2,4,6}, 1: {1,3,5,7}
    const int j1 = lane, j2 = lane + 32;        // scalar lanes for masked rows
    const int i1 = ((j1 >> 2) * 33) * 4 + (j1 & 3);
    const int i2 = ((j2 >> 2) * 33) * 4 + (j2 & 3);

    #pragma unroll 4
    for (int p = 0; p < 32; ++p) {
        if ((mbits >> p) & 1u) {
            // masked: coalesced scalar load of lbsw row (220 B, 4B-aligned)
            int np = wbase + p;
            if (np >= N) continue;
            const float* row = lbsw + (long)np * J;
            wsf[i1 + p * 4] = row[j1];
            if (j2 < 56)
                wsf[i2 + p * 4] = (j2 < J) ? row[j2] : 0.0f;
        } else {
            // unmasked: cooperative trilinear gather (broadcast po/pw reads)
            float4 acc = make_float4(0.f, 0.f, 0.f, 0.f);
            float4 v;
            v = vt4[s_po[warp][half + 0][p] + c]; acc = fma4(s_pw[warp][half + 0][p], v, acc);
            v = vt4[s_po[warp][half + 2][p] + c]; acc = fma4(s_pw[warp][half + 2][p], v, acc);
            v = vt4[s_po[warp][half + 4][p] + c]; acc = fma4(s_pw[warp][half + 4][p], v, acc);
            v = vt4[s_po[warp][half + 6][p] + c]; acc = fma4(s_pw[warp][half + 6][p], v, acc);
            acc.x += __shfl_xor_sync(0xffffffffu, acc.x, 16);
            acc.y += __shfl_xor_sync(0xffffffffu, acc.y, 16);
            acc.z += __shfl_xor_sync(0xffffffffu, acc.z, 16);
            acc.w += __shfl_xor_sync(0xffffffffu, acc.w, 16);
            if (half == 0 && c < 14) s_ws[warp][c][p] = acc;
        }
    }
    __syncwarp();

    // ----- phase 2: branch-free packed-f32x2 blend -----
    unsigned long long A[8], C[8];
    #pragma unroll
    for (int i = 0; i < 8; ++i) { A[i] = 0ull; C[i] = 0ull; }

    #pragma unroll
    for (int cc = 0; cc < 14; ++cc) {
        float4 w4 = s_ws[warp][cc][lane];
        int t = cc * 16;
        ACCW(w4.x, t);      ACCW(w4.y, t + 4);
        ACCW(w4.z, t + 8);  ACCW(w4.w, t + 12);
    }

    float2 a0l = u2f2(A[0]), a0h = u2f2(A[1]);
    float2 a1l = u2f2(A[2]), a1h = u2f2(A[3]);
    float2 a2l = u2f2(A[4]), a2h = u2f2(A[5]);
    float2 a3l = u2f2(A[6]), a3h = u2f2(A[7]);
    float4 A0 = {a0l.x, a0l.y, a0h.x, a0h.y};
    float4 A1 = {a1l.x, a1l.y, a1h.x, a1h.y};
    float4 A2 = {a2l.x, a2l.y, a2h.x, a2h.y};
    float4 A3 = {a3l.x, a3l.y, a3h.x, a3h.y};
    float2 c0l = u2f2(C[0]), c0h = u2f2(C[1]);
    float2 c1l = u2f2(C[2]), c1h = u2f2(C[3]);
    float2 c2l = u2f2(C[4]), c2h = u2f2(C[5]);
    float2 c3l = u2f2(C[6]), c3h = u2f2(C[7]);
    float4 C0 = {c0l.x, c0l.y, c0h.x, c0h.y};
    float4 C1 = {c1l.x, c1l.y, c1h.x, c1h.y};
    float4 C2 = {c2l.x, c2l.y, c2h.x, c2h.y};
    float4 C3 = {c3l.x, c3l.y, c3h.x, c3h.y};

    // xc_cano = w_tf_inv @ [xc, 1]
    float cx = A0.x * px + A0.y * py + A0.z * pz + A0.w;
    float cy = A1.x * px + A1.y * py + A1.z * pz + A1.w;
    float cz = A2.x * px + A2.y * py + A2.z * pz + A2.w;

    const long n3 = (long)nc * 3, i3 = idx * 3;
    float sx = cx - poseoff_ori[n3 + 0] + shape_off[i3 + 0] + pose_off[i3 + 0];
    float sy = cy - poseoff_ori[n3 + 1] + shape_off[i3 + 1] + pose_off[i3 + 1];
    float sz = cz - poseoff_ori[n3 + 2] + shape_off[i3 + 2] + pose_off[i3 + 2];

    if (n < N) {
        out_xd[i3 + 0] = C0.x * sx + C0.y * sy + C0.z * sz + C0.w;
        out_xd[i3 + 1] = C1.x * sx + C1.y * sy + C1.z * sz + C1.w;
        out_xd[i3 + 2] = C2.x * sx + C2.y * sy + C2.z * sz + C2.w;

        float4* ow = ((float4*)out_w) + idx * 4;
        float4 R;
        R.x = C0.x*A0.x + C0.y*A1.x + C0.z*A2.x + C0.w*A3.x;
        R.y = C0.x*A0.y + C0.y*A1.y + C0.z*A2.y + C0.w*A3.y;
        R.z = C0.x*A0.z + C0.y*A1.z + C0.z*A2.z + C0.w*A3.z;
        R.w = C0.x*A0.w + C0.y*A1.w + C0.z*A2.w + C0.w*A3.w;
        ow[0] = R;
        R.x = C1.x*A0.x + C1.y*A1.x + C1.z*A2.x + C1.w*A3.x;
        R.y = C1.x*A0.y + C1.y*A1.y + C1.z*A2.y + C1.w*A3.y;
        R.z = C1.x*A0.z + C1.y*A1.z + C1.z*A2.z + C1.w*A3.z;
        R.w = C1.x*A0.w + C1.y*A1.w + C1.z*A2.w + C1.w*A3.w;
        ow[1] = R;
        R.x = C2.x*A0.x + C2.y*A1.x + C2.z*A2.x + C2.w*A3.x;
        R.y = C2.x*A0.y + C2.y*A1.y + C2.z*A2.y + C2.w*A3.y;
        R.z = C2.x*A0.z + C2.y*A1.z + C2.z*A2.z + C2.w*A3.z;
        R.w = C2.x*A0.w + C2.y*A1.w + C2.z*A2.w + C2.w*A3.w;
        ow[2] = R;
        R.x = C3.x*A0.x + C3.y*A1.x + C3.z*A2.x + C3.w*A3.x;
        R.y = C3.x*A0.y + C3.y*A1.y + C3.z*A2.y + C3.w*A3.y;
        R.z = C3.x*A0.z + C3.y*A1.z + C3.z*A2.z + C3.w*A3.z;
        R.w = C3.x*A0.w + C3.y*A1.w + C3.z*A2.w + C3.w*A3.w;
        ow[3] = R;
    }
}

// ---------------------------------------------------------------------------
// Host: resolve inputs by exact element count (ordering-independent binding).
// ---------------------------------------------------------------------------
extern "C" void kernel_launch(void* const* d_in, const int* in_sizes, int n_in,
                              void* d_out, int out_size) {
    const float *tfs = nullptr, *tfs_inv = nullptr, *poseoff_ori = nullptr,
                *lbsw = nullptr, *vol = nullptr;
    const void  *mask = nullptr;
    const float *p3M[3] = {nullptr, nullptr, nullptr};
    const float *psm[2] = {nullptr, nullptr};
    int c3 = 0, cs = 0;
    int idx_mask = -1, idx_first3M = -1;

    for (int i = 0; i < n_in; i++) {
        switch (in_sizes[i]) {
            case 3520:     tfs = (const float*)d_in[i]; break;
            case 880:      tfs_inv = (const float*)d_in[i]; break;
            case 750000:   poseoff_ori = (const float*)d_in[i]; break;
            case 13750000: lbsw = (const float*)d_in[i]; break;
            case 250000:   mask = d_in[i]; idx_mask = i; break;
            case 3604480:  vol = (const float*)d_in[i]; break;
            case 3:        if (cs < 2) psm[cs++] = (const float*)d_in[i]; break;
            case 3000000:
                if (c3 == 0) idx_first3M = i;
                if (c3 < 3) p3M[c3++] = (const float*)d_in[i];
                break;
            default: break;
        }
    }

    const int J = 55, N = 250000, B = 4;

    const float* xc        = (idx_mask >= 0 && idx_first3M >= 0 && idx_mask < idx_first3M)
                             ? p3M[2] : p3M[0];
    const float* shape_off = (xc == p3M[0]) ? p3M[1] : p3M[0];
    const float* pose_off  = (xc == p3M[0]) ? p3M[2] : p3M[1];
    const float* offk = psm[0];
    const float* sclk = psm[1];

    float* out_xd = (float*)d_out;
    float* out_w  = out_xd + (size_t)B * N * 3;

    reset_flag_kernel<<<1, 1>>>();
    detect_mask_kernel<<<(65536 + 255) / 256, 256>>>((const unsigned char*)mask, N);
    transpose_vol_kernel<<<NVOX / 64, 256>>>(vol, J);

    dim3 grid((N + 127) / 128, B);
    deform_kernel<<<grid, 128>>>(xc, shape_off, pose_off, tfs, tfs_inv,
                                 poseoff_ori, mask, lbsw, offk, sclk,
                                 out_xd, out_w, N, J);
}

// round 10
// speedup vs baseline: 1.4931x; 1.2103x over previous
#include <cuda_runtime.h>
#include <cstdint>

#define DV 16
#define HV 64
#define WV 64
#define NVOX (DV*HV*WV)   /* 65536 voxels */
#define NMAX 250000
#define JJ   55

// Scratch (no allocations allowed)
__device__ __align__(16) float4 g_mv[NVOX * 20];   // 20MB: per-voxel [A, C0..C3] rows
__device__ __align__(16) float4 g_pm[NMAX * 20];   // 80MB: per-point  [A, C0..C3] rows (masked only)
__device__ int g_mask_is_u8;

// ---------------------------------------------------------------------------
// helpers
// ---------------------------------------------------------------------------
static __device__ __forceinline__ unsigned long long ffma2(
    unsigned long long a, unsigned long long b, unsigned long long c) {
    unsigned long long d;
    asm("fma.rn.f32x2 %0, %1, %2, %3;" : "=l"(d) : "l"(a), "l"(b), "l"(c));
    return d;
}
static __device__ __forceinline__ unsigned long long splat2(float w) {
    unsigned long long d;
    asm("mov.b64 %0, {%1, %1};" : "=l"(d) : "f"(w));
    return d;
}
static __device__ __forceinline__ float4 pack2(unsigned long long a, unsigned long long b) {
    float4 r;
    asm("mov.b64 {%0, %1}, %2;" : "=f"(r.x), "=f"(r.y) : "l"(a));
    asm("mov.b64 {%0, %1}, %2;" : "=f"(r.z), "=f"(r.w) : "l"(b));
    return r;
}
static __device__ __forceinline__ float4 fma4(float a, float4 b, float4 c) {
    float4 r;
    r.x = fmaf(a, b.x, c.x); r.y = fmaf(a, b.y, c.y);
    r.z = fmaf(a, b.z, c.z); r.w = fmaf(a, b.w, c.w);
    return r;
}

// ---------------------------------------------------------------------------
// mask dtype detection: int32 0/1 has zero bytes at offsets %4!=0; u8 doesn't.
// ---------------------------------------------------------------------------
__global__ void reset_flag_kernel() { g_mask_is_u8 = 0; }

__global__ void detect_mask_kernel(const unsigned char* __restrict__ m, int N) {
    int i = blockIdx.x * 256 + threadIdx.x;
    int limit = N < 65536 ? N : 65536;
    if (i < limit && (i & 3) != 0 && m[i] != 0)
        atomicOr(&g_mask_is_u8, 1);
}

static __device__ __forceinline__ bool read_mask(const void* mask_raw, int n) {
    if (g_mask_is_u8) return ((const unsigned char*)mask_raw)[n] != 0;
    return ((const int*)mask_raw)[n] != 0;
}

// ---------------------------------------------------------------------------
// P1: per-voxel pre-blend. blockIdx.y = m (0 = tfs_inv, 1..4 = tfs batch m-1).
// M[v] = sum_j vol[j][v] * T_j   (vol reads fully coalesced in original layout)
// ---------------------------------------------------------------------------
__global__ void __launch_bounds__(256) preblend_vox_kernel(
    const float* __restrict__ vol, const float* __restrict__ tfs,
    const float* __restrict__ tfs_inv)
{
    const int m = blockIdx.y;
    const int v = blockIdx.x * 256 + threadIdx.x;
    __shared__ float4 s_T[JJ * 4];
    {
        const float* src = (m == 0) ? tfs_inv : tfs + (m - 1) * JJ * 16;
        float* st = (float*)s_T;
        for (int e = threadIdx.x; e < JJ * 16; e += 256) st[e] = src[e];
    }
    __syncthreads();

    unsigned long long A0=0,A1=0,A2=0,A3=0,A4=0,A5=0,A6=0,A7=0;
    #pragma unroll 5
    for (int j = 0; j < JJ; ++j) {
        unsigned long long s = splat2(vol[j * NVOX + v]);
        const ulonglong2* rp = (const ulonglong2*)&s_T[j * 4];
        ulonglong2 r0 = rp[0], r1 = rp[1], r2 = rp[2], r3 = rp[3];
        A0 = ffma2(s, r0.x, A0); A1 = ffma2(s, r0.y, A1);
        A2 = ffma2(s, r1.x, A2); A3 = ffma2(s, r1.y, A3);
        A4 = ffma2(s, r2.x, A4); A5 = ffma2(s, r2.y, A5);
        A6 = ffma2(s, r3.x, A6); A7 = ffma2(s, r3.y, A7);
    }
    float4* out = &g_mv[v * 20 + m * 4];
    out[0] = pack2(A0, A1); out[1] = pack2(A2, A3);
    out[2] = pack2(A4, A5); out[3] = pack2(A6, A7);
}

// ---------------------------------------------------------------------------
// P2: per-point pre-blend for MASKED points.  block = (32 pts, 5 matrices).
// M[n] = sum_j lbsw[n][j] * T_j
// ---------------------------------------------------------------------------
__global__ void __launch_bounds__(160) preblend_pts_kernel(
    const float* __restrict__ lbsw, const float* __restrict__ tfs,
    const float* __restrict__ tfs_inv, const void* __restrict__ mask_raw, int N)
{
    __shared__ float4 s_T[5][JJ * 4];
    __shared__ float  s_w[JJ][33];
    const int tid = threadIdx.y * 32 + threadIdx.x;
    const int n0 = blockIdx.x * 32;
    {
        float* st = (float*)s_T;
        for (int e = tid; e < 5 * JJ * 16; e += 160) {
            int m = e / (JJ * 16), q = e - m * (JJ * 16);
            st[e] = (m == 0) ? tfs_inv[q] : tfs[(m - 1) * JJ * 16 + q];
        }
        int cnt = min(32, N - n0);
        for (int e = tid; e < cnt * JJ; e += 160) {
            int p = e / JJ, j = e - p * JJ;
            s_w[j][p] = lbsw[(long)n0 * JJ + e];     // fully coalesced
        }
    }
    __syncthreads();

    const int p = threadIdx.x, m = threadIdx.y;
    const int n = n0 + p;
    if (n >= N) return;
    if (!read_mask(mask_raw, n)) return;             // unmasked: never read

    unsigned long long A0=0,A1=0,A2=0,A3=0,A4=0,A5=0,A6=0,A7=0;
    #pragma unroll 5
    for (int j = 0; j < JJ; ++j) {
        unsigned long long s = splat2(s_w[j][p]);
        const ulonglong2* rp = (const ulonglong2*)&s_T[m][j * 4];
        ulonglong2 r0 = rp[0], r1 = rp[1], r2 = rp[2], r3 = rp[3];
        A0 = ffma2(s, r0.x, A0); A1 = ffma2(s, r0.y, A1);
        A2 = ffma2(s, r1.x, A2); A3 = ffma2(s, r1.y, A3);
        A4 = ffma2(s, r2.x, A4); A5 = ffma2(s, r2.y, A5);
        A6 = ffma2(s, r3.x, A6); A7 = ffma2(s, r3.y, A7);
    }
    float4* out = &g_pm[(long)n * 20 + m * 4];
    out[0] = pack2(A0, A1); out[1] = pack2(A2, A3);
    out[2] = pack2(A4, A5); out[3] = pack2(A6, A7);
}

// ---------------------------------------------------------------------------
// Main: 8 lanes per point. Lane k<4 builds A row k; lane k>=4 builds C_b row k-4
// by trilinear interp of pre-blended voxel matrices (or direct load if masked).
// Epilogue reassembles across the 8-lane group with shuffles. No shared memory.
// ---------------------------------------------------------------------------
__global__ void __launch_bounds__(256) deform_kernel(
    const float* __restrict__ xc, const float* __restrict__ shape_off,
    const float* __restrict__ pose_off, const float* __restrict__ poseoff_ori,
    const void* __restrict__ mask_raw,
    const float* __restrict__ offk, const float* __restrict__ sclk,
    float* __restrict__ out_xd, float* __restrict__ out_w, int N)
{
    const int b = blockIdx.y;
    const int g = threadIdx.x >> 3;            // point slot in block (0..31)
    const int k = threadIdx.x & 7;             // row slot within group
    const int n = blockIdx.x * 32 + g;
    const int nc = n < N ? n : N - 1;          // clamp; no early return (shuffles)
    const long idx = (long)b * N + nc;

    const bool msk = read_mask(mask_raw, nc);
    const float px = xc[idx * 3 + 0], py = xc[idx * 3 + 1], pz = xc[idx * 3 + 2];
    const int sel = (k < 4) ? k : (b + 1) * 4 + (k - 4);

    float4 acc;
    if (msk) {
        acc = g_pm[(long)nc * 20 + sel];
    } else {
        const float fx = (px + offk[0]) * sclk[0];
        const float fy = (py + offk[1]) * sclk[1];
        const float fz = (pz + offk[2]) * sclk[2];
        float ix = fminf(fmaxf((fx + 1.0f) * 0.5f * (float)(WV - 1), 0.0f), (float)(WV - 1));
        float iy = fminf(fmaxf((fy + 1.0f) * 0.5f * (float)(HV - 1), 0.0f), (float)(HV - 1));
        float iz = fminf(fmaxf((fz + 1.0f) * 0.5f * (float)(DV - 1), 0.0f), (float)(DV - 1));
        float xf = floorf(ix), yf = floorf(iy), zf = floorf(iz);
        float wx = ix - xf, wy = iy - yf, wz = iz - zf;
        int x0 = (int)xf, y0 = (int)yf, z0 = (int)zf;
        int x1 = min(x0 + 1, WV - 1), y1 = min(y0 + 1, HV - 1), z1 = min(z0 + 1, DV - 1);
        int r00 = (z0 * HV + y0) * WV, r01 = (z0 * HV + y1) * WV;
        int r10 = (z1 * HV + y0) * WV, r11 = (z1 * HV + y1) * WV;
        float mx = 1.0f - wx, my = 1.0f - wy, mz = 1.0f - wz;

        acc = make_float4(0.f, 0.f, 0.f, 0.f);
        acc = fma4(mz * my * mx, g_mv[(r00 + x0) * 20 + sel], acc);
        acc = fma4(mz * my * wx, g_mv[(r00 + x1) * 20 + sel], acc);
        acc = fma4(mz * wy * mx, g_mv[(r01 + x0) * 20 + sel], acc);
        acc = fma4(mz * wy * wx, g_mv[(r01 + x1) * 20 + sel], acc);
        acc = fma4(wz * my * mx, g_mv[(r10 + x0) * 20 + sel], acc);
        acc = fma4(wz * my * wx, g_mv[(r10 + x1) * 20 + sel], acc);
        acc = fma4(wz * wy * mx, g_mv[(r11 + x0) * 20 + sel], acc);
        acc = fma4(wz * wy * wx, g_mv[(r11 + x1) * 20 + sel], acc);
    }

    // ----- epilogue -----
    const unsigned F = 0xffffffffu;
    const int lane = threadIdx.x & 31;
    const int gbl  = lane & ~7;                // group base lane within warp

    // lanes k<4: a_k = A_k . [p,1];  k<3 add offsets
    float aval = acc.x * px + acc.y * py + acc.z * pz + acc.w;
    if (k < 3)
        aval += -poseoff_ori[(long)nc * 3 + k]
              + shape_off[idx * 3 + k] + pose_off[idx * 3 + k];

    float sx = __shfl_sync(F, aval, gbl + 0);
    float sy = __shfl_sync(F, aval, gbl + 1);
    float sz = __shfl_sync(F, aval, gbl + 2);

    // broadcast A rows (lanes gbl+0..3) to the whole group
    float4 A0, A1, A2, A3;
    A0.x = __shfl_sync(F, acc.x, gbl + 0); A0.y = __shfl_sync(F, acc.y, gbl + 0);
    A0.z = __shfl_sync(F, acc.z, gbl + 0); A0.w = __shfl_sync(F, acc.w, gbl + 0);
    A1.x = __shfl_sync(F, acc.x, gbl + 1); A1.y = __shfl_sync(F, acc.y, gbl + 1);
    A1.z = __shfl_sync(F, acc.z, gbl + 1); A1.w = __shfl_sync(F, acc.w, gbl + 1);
    A2.x = __shfl_sync(F, acc.x, gbl + 2); A2.y = __shfl_sync(F, acc.y, gbl + 2);
    A2.z = __shfl_sync(F, acc.z, gbl + 2); A2.w = __shfl_sync(F, acc.w, gbl + 2);
    A3.x = __shfl_sync(F, acc.x, gbl + 3); A3.y = __shfl_sync(F, acc.y, gbl + 3);
    A3.z = __shfl_sync(F, acc.z, gbl + 3); A3.w = __shfl_sync(F, acc.w, gbl + 3);

    if (n < N && k >= 4) {
        const int i = k - 4;                   // C row index
        float4 R;                              // R row i = C_i @ A
        R.x = acc.x * A0.x + acc.y * A1.x + acc.z * A2.x + acc.w * A3.x;
        R.y = acc.x * A0.y + acc.y * A1.y + acc.z * A2.y + acc.w * A3.y;
        R.z = acc.x * A0.z + acc.y * A1.z + acc.z * A2.z + acc.w * A3.z;
        R.w = acc.x * A0.w + acc.y * A1.w + acc.z * A2.w + acc.w * A3.w;
        ((float4*)out_w)[idx * 4 + i] = R;
        if (i < 3)
            out_xd[idx * 3 + i] = acc.x * sx + acc.y * sy + acc.z * sz + acc.w;
    }
}

// ---------------------------------------------------------------------------
// Host: resolve inputs by exact element count (ordering-independent binding).
// ---------------------------------------------------------------------------
extern "C" void kernel_launch(void* const* d_in, const int* in_sizes, int n_in,
                              void* d_out, int out_size) {
    const float *tfs = nullptr, *tfs_inv = nullptr, *poseoff_ori = nullptr,
                *lbsw = nullptr, *vol = nullptr;
    const void  *mask = nullptr;
    const float *p3M[3] = {nullptr, nullptr, nullptr};
    const float *psm[2] = {nullptr, nullptr};
    int c3 = 0, cs = 0;
    int idx_mask = -1, idx_first3M = -1;

    for (int i = 0; i < n_in; i++) {
        switch (in_sizes[i]) {
            case 3520:     tfs = (const float*)d_in[i]; break;
            case 880:      tfs_inv = (const float*)d_in[i]; break;
            case 750000:   poseoff_ori = (const float*)d_in[i]; break;
            case 13750000: lbsw = (const float*)d_in[i]; break;
            case 250000:   mask = d_in[i]; idx_mask = i; break;
            case 3604480:  vol = (const float*)d_in[i]; break;
            case 3:        if (cs < 2) psm[cs++] = (const float*)d_in[i]; break;
            case 3000000:
                if (c3 == 0) idx_first3M = i;
                if (c3 < 3) p3M[c3++] = (const float*)d_in[i];
                break;
            default: break;
        }
    }

    const int N = 250000, B = 4;

    const float* xc        = (idx_mask >= 0 && idx_first3M >= 0 && idx_mask < idx_first3M)
                             ? p3M[2] : p3M[0];
    const float* shape_off = (xc == p3M[0]) ? p3M[1] : p3M[0];
    const float* pose_off  = (xc == p3M[0]) ? p3M[2] : p3M[1];
    const float* offk = psm[0];
    const float* sclk = psm[1];

    float* out_xd = (float*)d_out;
    float* out_w  = out_xd + (size_t)B * N * 3;

    reset_flag_kernel<<<1, 1>>>();
    detect_mask_kernel<<<(65536 + 255) / 256, 256>>>((const unsigned char*)mask, N);

    dim3 g1(NVOX / 256, 5);
    preblend_vox_kernel<<<g1, 256>>>(vol, tfs, tfs_inv);

    dim3 b2(32, 5);
    preblend_pts_kernel<<<(N + 31) / 32, b2>>>(lbsw, tfs, tfs_inv, mask, N);

    dim3 g3((N + 31) / 32, B);
    deform_kernel<<<g3, 256>>>(xc, shape_off, pose_off, poseoff_ori, mask,
                               offk, sclk, out_xd, out_w, N);
}

// round 12
// speedup vs baseline: 1.6352x; 1.0952x over previous
#include <cuda_runtime.h>
#include <cstdint>

#define DV 16
#define HV 64
#define WV 64
#define NVOX (DV*HV*WV)   /* 65536 voxels */
#define NMAX 250000
#define JJ   55

// Scratch (no allocations allowed)
__device__ __align__(16) float4 g_mv[NVOX * 20];   // 20MB: per-voxel [A,C0..C3] rows
__device__ __align__(16) float4 g_pm[NMAX * 20];   // 80MB: per-point rows (masked only)
__device__ int g_midx[NMAX];                       // compacted masked indices
__device__ int g_cnt;
__device__ int g_mask_is_u8;

// ---------------------------------------------------------------------------
// helpers
// ---------------------------------------------------------------------------
static __device__ __forceinline__ unsigned long long ffma2(
    unsigned long long a, unsigned long long b, unsigned long long c) {
    unsigned long long d;
    asm("fma.rn.f32x2 %0, %1, %2, %3;" : "=l"(d) : "l"(a), "l"(b), "l"(c));
    return d;
}
static __device__ __forceinline__ unsigned long long splat2(float w) {
    unsigned long long d;
    asm("mov.b64 %0, {%1, %1};" : "=l"(d) : "f"(w));
    return d;
}
static __device__ __forceinline__ float4 pack2(unsigned long long a, unsigned long long b) {
    float4 r;
    asm("mov.b64 {%0, %1}, %2;" : "=f"(r.x), "=f"(r.y) : "l"(a));
    asm("mov.b64 {%0, %1}, %2;" : "=f"(r.z), "=f"(r.w) : "l"(b));
    return r;
}
static __device__ __forceinline__ float4 fma4(float a, float4 b, float4 c) {
    float4 r;
    r.x = fmaf(a, b.x, c.x); r.y = fmaf(a, b.y, c.y);
    r.z = fmaf(a, b.z, c.z); r.w = fmaf(a, b.w, c.w);
    return r;
}

// ---------------------------------------------------------------------------
// mask dtype detection + reset
// ---------------------------------------------------------------------------
__global__ void reset_flag_kernel() { g_mask_is_u8 = 0; g_cnt = 0; }

__global__ void detect_mask_kernel(const unsigned char* __restrict__ m, int N) {
    int i = blockIdx.x * 256 + threadIdx.x;
    int limit = N < 65536 ? N : 65536;
    if (i < limit && (i & 3) != 0 && m[i] != 0)
        atomicOr(&g_mask_is_u8, 1);
}

static __device__ __forceinline__ bool read_mask(const void* mask_raw, int n) {
    if (g_mask_is_u8) return ((const unsigned char*)mask_raw)[n] != 0;
    return ((const int*)mask_raw)[n] != 0;
}

// ---------------------------------------------------------------------------
// compact masked point indices (order nondeterministic; outputs keyed by n)
// ---------------------------------------------------------------------------
__global__ void compact_mask_kernel(const void* __restrict__ mask_raw, int N) {
    int i = blockIdx.x * 256 + threadIdx.x;
    if (i < N && read_mask(mask_raw, i)) {
        int slot = atomicAdd(&g_cnt, 1);
        g_midx[slot] = i;
    }
}

// ---------------------------------------------------------------------------
// P1: per-voxel pre-blend. blockIdx.y = m (0 = tfs_inv, 1..4 = tfs batch m-1).
// M[v] = sum_j vol[j][v] * T_j
// ---------------------------------------------------------------------------
__global__ void __launch_bounds__(256) preblend_vox_kernel(
    const float* __restrict__ vol, const float* __restrict__ tfs,
    const float* __restrict__ tfs_inv)
{
    const int m = blockIdx.y;
    const int v = blockIdx.x * 256 + threadIdx.x;
    __shared__ float4 s_T[JJ * 4];
    {
        const float* src = (m == 0) ? tfs_inv : tfs + (m - 1) * JJ * 16;
        float* st = (float*)s_T;
        for (int e = threadIdx.x; e < JJ * 16; e += 256) st[e] = src[e];
    }
    __syncthreads();

    unsigned long long A0=0,A1=0,A2=0,A3=0,A4=0,A5=0,A6=0,A7=0;
    #pragma unroll 5
    for (int j = 0; j < JJ; ++j) {
        unsigned long long s = splat2(vol[j * NVOX + v]);
        const ulonglong2* rp = (const ulonglong2*)&s_T[j * 4];
        ulonglong2 r0 = rp[0], r1 = rp[1], r2 = rp[2], r3 = rp[3];
        A0 = ffma2(s, r0.x, A0); A1 = ffma2(s, r0.y, A1);
        A2 = ffma2(s, r1.x, A2); A3 = ffma2(s, r1.y, A3);
        A4 = ffma2(s, r2.x, A4); A5 = ffma2(s, r2.y, A5);
        A6 = ffma2(s, r3.x, A6); A7 = ffma2(s, r3.y, A7);
    }
    float4* out = &g_mv[v * 20 + m * 4];
    out[0] = pack2(A0, A1); out[1] = pack2(A2, A3);
    out[2] = pack2(A4, A5); out[3] = pack2(A6, A7);
}

// ---------------------------------------------------------------------------
// P2: per-point pre-blend over the COMPACTED masked list.
// block = (32, 5): thread (p, m) handles compacted slots i0+p and i0+p+32
// for matrix m (s_T rows loaded once, shared by both points).
// ---------------------------------------------------------------------------
__global__ void __launch_bounds__(160) preblend_pts_kernel(
    const float* __restrict__ lbsw, const float* __restrict__ tfs,
    const float* __restrict__ tfs_inv)
{
    const int cnt = g_cnt;
    const int i0 = blockIdx.x * 64;
    if (i0 >= cnt) return;

    __shared__ float4 s_T[5][JJ * 4];
    __shared__ float  s_w[JJ][66];
    __shared__ int    s_idx[64];
    const int tid = threadIdx.y * 32 + threadIdx.x;
    {
        float* st = (float*)s_T;
        for (int e = tid; e < 5 * JJ * 16; e += 160) {
            int m = e / (JJ * 16), q = e - m * (JJ * 16);
            st[e] = (m == 0) ? tfs_inv[q] : tfs[(m - 1) * JJ * 16 + q];
        }
        if (tid < 64) s_idx[tid] = (i0 + tid < cnt) ? g_midx[i0 + tid] : -1;
    }
    __syncthreads();
    {
        int cnt2 = min(64, cnt - i0);
        for (int e = tid; e < cnt2 * JJ; e += 160) {
            int p = e / JJ, j = e - p * JJ;
            s_w[j][p] = lbsw[(long)s_idx[p] * JJ + j];   // contiguous per row
        }
    }
    __syncthreads();

    const int p = threadIdx.x, m = threadIdx.y;
    const int nA = s_idx[p], nB = s_idx[p + 32];

    unsigned long long A0=0,A1=0,A2=0,A3=0,A4=0,A5=0,A6=0,A7=0;
    unsigned long long B0=0,B1=0,B2=0,B3=0,B4=0,B5=0,B6=0,B7=0;
    #pragma unroll 5
    for (int j = 0; j < JJ; ++j) {
        const ulonglong2* rp = (const ulonglong2*)&s_T[m][j * 4];
        ulonglong2 r0 = rp[0], r1 = rp[1], r2 = rp[2], r3 = rp[3];
        unsigned long long sa = splat2(s_w[j][p]);
        unsigned long long sb = splat2(s_w[j][p + 32]);
        A0 = ffma2(sa, r0.x, A0); A1 = ffma2(sa, r0.y, A1);
        A2 = ffma2(sa, r1.x, A2); A3 = ffma2(sa, r1.y, A3);
        A4 = ffma2(sa, r2.x, A4); A5 = ffma2(sa, r2.y, A5);
        A6 = ffma2(sa, r3.x, A6); A7 = ffma2(sa, r3.y, A7);
        B0 = ffma2(sb, r0.x, B0); B1 = ffma2(sb, r0.y, B1);
        B2 = ffma2(sb, r1.x, B2); B3 = ffma2(sb, r1.y, B3);
        B4 = ffma2(sb, r2.x, B4); B5 = ffma2(sb, r2.y, B5);
        B6 = ffma2(sb, r3.x, B6); B7 = ffma2(sb, r3.y, B7);
    }
    if (nA >= 0) {
        float4* out = &g_pm[(long)nA * 20 + m * 4];
        out[0] = pack2(A0, A1); out[1] = pack2(A2, A3);
        out[2] = pack2(A4, A5); out[3] = pack2(A6, A7);
    }
    if (nB >= 0) {
        float4* out = &g_pm[(long)nB * 20 + m * 4];
        out[0] = pack2(B0, B1); out[1] = pack2(B2, B3);
        out[2] = pack2(B4, B5); out[3] = pack2(B6, B7);
    }
}

// ---------------------------------------------------------------------------
// Main (R10 structure — per-batch grid.y, batch-specific xc!):
// 8 lanes per point. Lane k<4 builds A row k; lane k>=4 builds C_b row k-4
// by trilinear interp of pre-blended voxel matrices (or direct load if masked).
// Epilogue reassembles across the 8-lane group with shuffles. No shared memory.
// ---------------------------------------------------------------------------
__global__ void __launch_bounds__(256) deform_kernel(
    const float* __restrict__ xc, const float* __restrict__ shape_off,
    const float* __restrict__ pose_off, const float* __restrict__ poseoff_ori,
    const void* __restrict__ mask_raw,
    const float* __restrict__ offk, const float* __restrict__ sclk,
    float* __restrict__ out_xd, float* __restrict__ out_w, int N)
{
    const int b = blockIdx.y;
    const int g = threadIdx.x >> 3;            // point slot in block (0..31)
    const int k = threadIdx.x & 7;             // row slot within group
    const int n = blockIdx.x * 32 + g;
    const int nc = n < N ? n : N - 1;          // clamp; no early return (shuffles)
    const long idx = (long)b * N + nc;

    const bool msk = read_mask(mask_raw, nc);
    const float px = xc[idx * 3 + 0], py = xc[idx * 3 + 1], pz = xc[idx * 3 + 2];
    const int sel = (k < 4) ? k : (b + 1) * 4 + (k - 4);

    float4 acc;
    if (msk) {
        acc = g_pm[(long)nc * 20 + sel];
    } else {
        const float fx = (px + offk[0]) * sclk[0];
        const float fy = (py + offk[1]) * sclk[1];
        const float fz = (pz + offk[2]) * sclk[2];
        float ix = fminf(fmaxf((fx + 1.0f) * 0.5f * (float)(WV - 1), 0.0f), (float)(WV - 1));
        float iy = fminf(fmaxf((fy + 1.0f) * 0.5f * (float)(HV - 1), 0.0f), (float)(HV - 1));
        float iz = fminf(fmaxf((fz + 1.0f) * 0.5f * (float)(DV - 1), 0.0f), (float)(DV - 1));
        float xf = floorf(ix), yf = floorf(iy), zf = floorf(iz);
        float wx = ix - xf, wy = iy - yf, wz = iz - zf;
        int x0 = (int)xf, y0 = (int)yf, z0 = (int)zf;
        int x1 = min(x0 + 1, WV - 1), y1 = min(y0 + 1, HV - 1), z1 = min(z0 + 1, DV - 1);
        int r00 = (z0 * HV + y0) * WV, r01 = (z0 * HV + y1) * WV;
        int r10 = (z1 * HV + y0) * WV, r11 = (z1 * HV + y1) * WV;
        float mx = 1.0f - wx, my = 1.0f - wy, mz = 1.0f - wz;

        acc = make_float4(0.f, 0.f, 0.f, 0.f);
        acc = fma4(mz * my * mx, g_mv[(r00 + x0) * 20 + sel], acc);
        acc = fma4(mz * my * wx, g_mv[(r00 + x1) * 20 + sel], acc);
        acc = fma4(mz * wy * mx, g_mv[(r01 + x0) * 20 + sel], acc);
        acc = fma4(mz * wy * wx, g_mv[(r01 + x1) * 20 + sel], acc);
        acc = fma4(wz * my * mx, g_mv[(r10 + x0) * 20 + sel], acc);
        acc = fma4(wz * my * wx, g_mv[(r10 + x1) * 20 + sel], acc);
        acc = fma4(wz * wy * mx, g_mv[(r11 + x0) * 20 + sel], acc);
        acc = fma4(wz * wy * wx, g_mv[(r11 + x1) * 20 + sel], acc);
    }

    // ----- epilogue -----
    const unsigned F = 0xffffffffu;
    const int lane = threadIdx.x & 31;
    const int gbl  = lane & ~7;                // group base lane within warp

    // lanes k<4: a_k = A_k . [p,1];  k<3 add offsets
    float aval = acc.x * px + acc.y * py + acc.z * pz + acc.w;
    if (k < 3)
        aval += -poseoff_ori[(long)nc * 3 + k]
              + shape_off[idx * 3 + k] + pose_off[idx * 3 + k];

    float sx = __shfl_sync(F, aval, gbl + 0);
    float sy = __shfl_sync(F, aval, gbl + 1);
    float sz = __shfl_sync(F, aval, gbl + 2);

    // broadcast A rows (lanes gbl+0..3) to the whole group
    float4 A0, A1, A2, A3;
    A0.x = __shfl_sync(F, acc.x, gbl + 0); A0.y = __shfl_sync(F, acc.y, gbl + 0);
    A0.z = __shfl_sync(F, acc.z, gbl + 0); A0.w = __shfl_sync(F, acc.w, gbl + 0);
    A1.x = __shfl_sync(F, acc.x, gbl + 1); A1.y = __shfl_sync(F, acc.y, gbl + 1);
    A1.z = __shfl_sync(F, acc.z, gbl + 1); A1.w = __shfl_sync(F, acc.w, gbl + 1);
    A2.x = __shfl_sync(F, acc.x, gbl + 2); A2.y = __shfl_sync(F, acc.y, gbl + 2);
    A2.z = __shfl_sync(F, acc.z, gbl + 2); A2.w = __shfl_sync(F, acc.w, gbl + 2);
    A3.x = __shfl_sync(F, acc.x, gbl + 3); A3.y = __shfl_sync(F, acc.y, gbl + 3);
    A3.z = __shfl_sync(F, acc.z, gbl + 3); A3.w = __shfl_sync(F, acc.w, gbl + 3);

    if (n < N && k >= 4) {
        const int i = k - 4;                   // C row index
        float4 R;                              // R row i = C_i @ A
        R.x = acc.x * A0.x + acc.y * A1.x + acc.z * A2.x + acc.w * A3.x;
        R.y = acc.x * A0.y + acc.y * A1.y + acc.z * A2.y + acc.w * A3.y;
        R.z = acc.x * A0.z + acc.y * A1.z + acc.z * A2.z + acc.w * A3.z;
        R.w = acc.x * A0.w + acc.y * A1.w + acc.z * A2.w + acc.w * A3.w;
        ((float4*)out_w)[idx * 4 + i] = R;
        if (i < 3)
            out_xd[idx * 3 + i] = acc.x * sx + acc.y * sy + acc.z * sz + acc.w;
    }
}

// ---------------------------------------------------------------------------
// Host: resolve inputs by exact element count (ordering-independent binding).
// ---------------------------------------------------------------------------
extern "C" void kernel_launch(void* const* d_in, const int* in_sizes, int n_in,
                              void* d_out, int out_size) {
    const float *tfs = nullptr, *tfs_inv = nullptr, *poseoff_ori = nullptr,
                *lbsw = nullptr, *vol = nullptr;
    const void  *mask = nullptr;
    const float *p3M[3] = {nullptr, nullptr, nullptr};
    const float *psm[2] = {nullptr, nullptr};
    int c3 = 0, cs = 0;
    int idx_mask = -1, idx_first3M = -1;

    for (int i = 0; i < n_in; i++) {
        switch (in_sizes[i]) {
            case 3520:     tfs = (const float*)d_in[i]; break;
            case 880:      tfs_inv = (const float*)d_in[i]; break;
            case 750000:   poseoff_ori = (const float*)d_in[i]; break;
            case 13750000: lbsw = (const float*)d_in[i]; break;
            case 250000:   mask = d_in[i]; idx_mask = i; break;
            case 3604480:  vol = (const float*)d_in[i]; break;
            case 3:        if (cs < 2) psm[cs++] = (const float*)d_in[i]; break;
            case 3000000:
                if (c3 == 0) idx_first3M = i;
                if (c3 < 3) p3M[c3++] = (const float*)d_in[i];
                break;
            default: break;
        }
    }

    const int N = 250000, B = 4;

    const float* xc        = (idx_mask >= 0 && idx_first3M >= 0 && idx_mask < idx_first3M)
                             ? p3M[2] : p3M[0];
    const float* shape_off = (xc == p3M[0]) ? p3M[1] : p3M[0];
    const float* pose_off  = (xc == p3M[0]) ? p3M[2] : p3M[1];
    const float* offk = psm[0];
    const float* sclk = psm[1];

    float* out_xd = (float*)d_out;
    float* out_w  = out_xd + (size_t)B * N * 3;

    reset_flag_kernel<<<1, 1>>>();
    detect_mask_kernel<<<(65536 + 255) / 256, 256>>>((const unsigned char*)mask, N);
    compact_mask_kernel<<<(N + 255) / 256, 256>>>(mask, N);

    dim3 g1(NVOX / 256, 5);
    preblend_vox_kernel<<<g1, 256>>>(vol, tfs, tfs_inv);

    dim3 b2(32, 5);
    preblend_pts_kernel<<<(N + 63) / 64, b2>>>(lbsw, tfs, tfs_inv);

    dim3 g3((N + 31) / 32, 4);
    deform_kernel<<<g3, 256>>>(xc, shape_off, pose_off, poseoff_ori, mask,
                               offk, sclk, out_xd, out_w, N);
}

// round 13
// speedup vs baseline: 1.6887x; 1.0327x over previous
#include <cuda_runtime.h>
#include <cstdint>

#define DV 16
#define HV 64
#define WV 64
#define NVOX (DV*HV*WV)   /* 65536 voxels */
#define NMAX 250000
#define JJ   55

// Scratch (no allocations allowed)
__device__ __align__(16) float4 g_mv[NVOX * 20];   // 20MB: per-voxel [A,C0..C3] rows
__device__ __align__(16) float4 g_pm[NMAX * 20];   // 80MB: per-point rows (masked only)
__device__ int g_midx[NMAX];                       // compacted masked indices
__device__ int g_cnt;
__device__ int g_mask_is_u8;

// ---------------------------------------------------------------------------
// helpers
// ---------------------------------------------------------------------------
static __device__ __forceinline__ unsigned long long ffma2(
    unsigned long long a, unsigned long long b, unsigned long long c) {
    unsigned long long d;
    asm("fma.rn.f32x2 %0, %1, %2, %3;" : "=l"(d) : "l"(a), "l"(b), "l"(c));
    return d;
}
static __device__ __forceinline__ unsigned long long splat2(float w) {
    unsigned long long d;
    asm("mov.b64 %0, {%1, %1};" : "=l"(d) : "f"(w));
    return d;
}
static __device__ __forceinline__ float4 pack2(unsigned long long a, unsigned long long b) {
    float4 r;
    asm("mov.b64 {%0, %1}, %2;" : "=f"(r.x), "=f"(r.y) : "l"(a));
    asm("mov.b64 {%0, %1}, %2;" : "=f"(r.z), "=f"(r.w) : "l"(b));
    return r;
}

// ---------------------------------------------------------------------------
// mask dtype detection + reset
// ---------------------------------------------------------------------------
__global__ void reset_flag_kernel() { g_mask_is_u8 = 0; g_cnt = 0; }

__global__ void detect_mask_kernel(const unsigned char* __restrict__ m, int N) {
    int i = blockIdx.x * 256 + threadIdx.x;
    int limit = N < 65536 ? N : 65536;
    if (i < limit && (i & 3) != 0 && m[i] != 0)
        atomicOr(&g_mask_is_u8, 1);
}

static __device__ __forceinline__ bool read_mask(const void* mask_raw, int n) {
    if (g_mask_is_u8) return ((const unsigned char*)mask_raw)[n] != 0;
    return ((const int*)mask_raw)[n] != 0;
}

// ---------------------------------------------------------------------------
// compact masked point indices (order nondeterministic; outputs keyed by n)
// ---------------------------------------------------------------------------
__global__ void compact_mask_kernel(const void* __restrict__ mask_raw, int N) {
    int i = blockIdx.x * 256 + threadIdx.x;
    if (i < N && read_mask(mask_raw, i)) {
        int slot = atomicAdd(&g_cnt, 1);
        g_midx[slot] = i;
    }
}

// ---------------------------------------------------------------------------
// P1: per-voxel pre-blend, TWO voxels per thread (amortizes s_T LDS).
// blockIdx.y = m (0 = tfs_inv, 1..4 = tfs batch m-1).  M[v] = sum_j vol[j][v]*T_j
// ---------------------------------------------------------------------------
__global__ void __launch_bounds__(256) preblend_vox_kernel(
    const float* __restrict__ vol, const float* __restrict__ tfs,
    const float* __restrict__ tfs_inv)
{
    const int m = blockIdx.y;
    const int v = (blockIdx.x * 256 + threadIdx.x) * 2;
    __shared__ float4 s_T[JJ * 4];
    {
        const float* src = (m == 0) ? tfs_inv : tfs + (m - 1) * JJ * 16;
        float* st = (float*)s_T;
        for (int e = threadIdx.x; e < JJ * 16; e += 256) st[e] = src[e];
    }
    __syncthreads();

    unsigned long long A0=0,A1=0,A2=0,A3=0,A4=0,A5=0,A6=0,A7=0;
    unsigned long long B0=0,B1=0,B2=0,B3=0,B4=0,B5=0,B6=0,B7=0;
    #pragma unroll 5
    for (int j = 0; j < JJ; ++j) {
        float2 w2 = *(const float2*)&vol[j * NVOX + v];
        unsigned long long sa = splat2(w2.x);
        unsigned long long sb = splat2(w2.y);
        const ulonglong2* rp = (const ulonglong2*)&s_T[j * 4];
        ulonglong2 r0 = rp[0], r1 = rp[1], r2 = rp[2], r3 = rp[3];
        A0 = ffma2(sa, r0.x, A0); A1 = ffma2(sa, r0.y, A1);
        A2 = ffma2(sa, r1.x, A2); A3 = ffma2(sa, r1.y, A3);
        A4 = ffma2(sa, r2.x, A4); A5 = ffma2(sa, r2.y, A5);
        A6 = ffma2(sa, r3.x, A6); A7 = ffma2(sa, r3.y, A7);
        B0 = ffma2(sb, r0.x, B0); B1 = ffma2(sb, r0.y, B1);
        B2 = ffma2(sb, r1.x, B2); B3 = ffma2(sb, r1.y, B3);
        B4 = ffma2(sb, r2.x, B4); B5 = ffma2(sb, r2.y, B5);
        B6 = ffma2(sb, r3.x, B6); B7 = ffma2(sb, r3.y, B7);
    }
    float4* out = &g_mv[v * 20 + m * 4];
    out[0] = pack2(A0, A1); out[1] = pack2(A2, A3);
    out[2] = pack2(A4, A5); out[3] = pack2(A6, A7);
    out = &g_mv[(v + 1) * 20 + m * 4];
    out[0] = pack2(B0, B1); out[1] = pack2(B2, B3);
    out[2] = pack2(B4, B5); out[3] = pack2(B6, B7);
}

// ---------------------------------------------------------------------------
// P2: per-point pre-blend over the COMPACTED masked list.
// block = (32, 5): thread (p, m) handles compacted slots i0+p and i0+p+32
// for matrix m (s_T rows loaded once, shared by both points).
// ---------------------------------------------------------------------------
__global__ void __launch_bounds__(160) preblend_pts_kernel(
    const float* __restrict__ lbsw, const float* __restrict__ tfs,
    const float* __restrict__ tfs_inv)
{
    const int cnt = g_cnt;
    const int i0 = blockIdx.x * 64;
    if (i0 >= cnt) return;

    __shared__ float4 s_T[5][JJ * 4];
    __shared__ float  s_w[JJ][66];
    __shared__ int    s_idx[64];
    const int tid = threadIdx.y * 32 + threadIdx.x;
    {
        float* st = (float*)s_T;
        for (int e = tid; e < 5 * JJ * 16; e += 160) {
            int m = e / (JJ * 16), q = e - m * (JJ * 16);
            st[e] = (m == 0) ? tfs_inv[q] : tfs[(m - 1) * JJ * 16 + q];
        }
        if (tid < 64) s_idx[tid] = (i0 + tid < cnt) ? g_midx[i0 + tid] : -1;
    }
    __syncthreads();
    {
        int cnt2 = min(64, cnt - i0);
        for (int e = tid; e < cnt2 * JJ; e += 160) {
            int p = e / JJ, j = e - p * JJ;
            s_w[j][p] = lbsw[(long)s_idx[p] * JJ + j];   // contiguous per row
        }
    }
    __syncthreads();

    const int p = threadIdx.x, m = threadIdx.y;
    const int nA = s_idx[p], nB = s_idx[p + 32];

    unsigned long long A0=0,A1=0,A2=0,A3=0,A4=0,A5=0,A6=0,A7=0;
    unsigned long long B0=0,B1=0,B2=0,B3=0,B4=0,B5=0,B6=0,B7=0;
    #pragma unroll 5
    for (int j = 0; j < JJ; ++j) {
        const ulonglong2* rp = (const ulonglong2*)&s_T[m][j * 4];
        ulonglong2 r0 = rp[0], r1 = rp[1], r2 = rp[2], r3 = rp[3];
        unsigned long long sa = splat2(s_w[j][p]);
        unsigned long long sb = splat2(s_w[j][p + 32]);
        A0 = ffma2(sa, r0.x, A0); A1 = ffma2(sa, r0.y, A1);
        A2 = ffma2(sa, r1.x, A2); A3 = ffma2(sa, r1.y, A3);
        A4 = ffma2(sa, r2.x, A4); A5 = ffma2(sa, r2.y, A5);
        A6 = ffma2(sa, r3.x, A6); A7 = ffma2(sa, r3.y, A7);
        B0 = ffma2(sb, r0.x, B0); B1 = ffma2(sb, r0.y, B1);
        B2 = ffma2(sb, r1.x, B2); B3 = ffma2(sb, r1.y, B3);
        B4 = ffma2(sb, r2.x, B4); B5 = ffma2(sb, r2.y, B5);
        B6 = ffma2(sb, r3.x, B6); B7 = ffma2(sb, r3.y, B7);
    }
    if (nA >= 0) {
        float4* out = &g_pm[(long)nA * 20 + m * 4];
        out[0] = pack2(A0, A1); out[1] = pack2(A2, A3);
        out[2] = pack2(A4, A5); out[3] = pack2(A6, A7);
    }
    if (nB >= 0) {
        float4* out = &g_pm[(long)nB * 20 + m * 4];
        out[0] = pack2(B0, B1); out[1] = pack2(B2, B3);
        out[2] = pack2(B4, B5); out[3] = pack2(B6, B7);
    }
}

// ---------------------------------------------------------------------------
// Main (per-batch grid.y, batch-specific xc):
// 8 lanes per point. Lane k<4 builds A row k; lane k>=4 builds C_b row k-4
// by packed-f32x2 trilinear interp of pre-blended voxel matrices
// (or direct load if masked). Epilogue reassembles across the 8-lane group.
// ---------------------------------------------------------------------------
__global__ void __launch_bounds__(256) deform_kernel(
    const float* __restrict__ xc, const float* __restrict__ shape_off,
    const float* __restrict__ pose_off, const float* __restrict__ poseoff_ori,
    const void* __restrict__ mask_raw,
    const float* __restrict__ offk, const float* __restrict__ sclk,
    float* __restrict__ out_xd, float* __restrict__ out_w, int N)
{
    const int b = blockIdx.y;
    const int g = threadIdx.x >> 3;            // point slot in block (0..31)
    const int k = threadIdx.x & 7;             // row slot within group
    const int n = blockIdx.x * 32 + g;
    const int nc = n < N ? n : N - 1;          // clamp; no early return (shuffles)
    const long idx = (long)b * N + nc;

    const bool msk = read_mask(mask_raw, nc);
    const float px = xc[idx * 3 + 0], py = xc[idx * 3 + 1], pz = xc[idx * 3 + 2];
    const int sel = (k < 4) ? k : (b + 1) * 4 + (k - 4);

    float4 acc;
    if (msk) {
        acc = g_pm[(long)nc * 20 + sel];
    } else {
        const float fx = (px + offk[0]) * sclk[0];
        const float fy = (py + offk[1]) * sclk[1];
        const float fz = (pz + offk[2]) * sclk[2];
        float ix = fminf(fmaxf((fx + 1.0f) * 0.5f * (float)(WV - 1), 0.0f), (float)(WV - 1));
        float iy = fminf(fmaxf((fy + 1.0f) * 0.5f * (float)(HV - 1), 0.0f), (float)(HV - 1));
        float iz = fminf(fmaxf((fz + 1.0f) * 0.5f * (float)(DV - 1), 0.0f), (float)(DV - 1));
        float xf = floorf(ix), yf = floorf(iy), zf = floorf(iz);
        float wx = ix - xf, wy = iy - yf, wz = iz - zf;
        int x0 = (int)xf, y0 = (int)yf, z0 = (int)zf;
        int x1 = min(x0 + 1, WV - 1), y1 = min(y0 + 1, HV - 1), z1 = min(z0 + 1, DV - 1);
        int r00 = (z0 * HV + y0) * WV, r01 = (z0 * HV + y1) * WV;
        int r10 = (z1 * HV + y0) * WV, r11 = (z1 * HV + y1) * WV;
        float mx = 1.0f - wx, my = 1.0f - wy, mz = 1.0f - wz;

        int   vs[8];
        float cw[8];
        vs[0] = r00 + x0; cw[0] = mz * my * mx;
        vs[1] = r00 + x1; cw[1] = mz * my * wx;
        vs[2] = r01 + x0; cw[2] = mz * wy * mx;
        vs[3] = r01 + x1; cw[3] = mz * wy * wx;
        vs[4] = r10 + x0; cw[4] = wz * my * mx;
        vs[5] = r10 + x1; cw[5] = wz * my * wx;
        vs[6] = r11 + x0; cw[6] = wz * wy * mx;
        vs[7] = r11 + x1; cw[7] = wz * wy * wx;

        unsigned long long a0 = 0ull, a1 = 0ull;
        #pragma unroll
        for (int t = 0; t < 8; ++t) {
            ulonglong2 r = *(const ulonglong2*)&g_mv[(long)vs[t] * 20 + sel];
            unsigned long long s = splat2(cw[t]);
            a0 = ffma2(s, r.x, a0);
            a1 = ffma2(s, r.y, a1);
        }
        acc = pack2(a0, a1);
    }

    // ----- epilogue -----
    const unsigned F = 0xffffffffu;
    const int lane = threadIdx.x & 31;
    const int gbl  = lane & ~7;                // group base lane within warp

    // lanes k<4: a_k = A_k . [p,1];  k<3 add offsets
    float aval = acc.x * px + acc.y * py + acc.z * pz + acc.w;
    if (k < 3)
        aval += -poseoff_ori[(long)nc * 3 + k]
              + shape_off[idx * 3 + k] + pose_off[idx * 3 + k];

    float sx = __shfl_sync(F, aval, gbl + 0);
    float sy = __shfl_sync(F, aval, gbl + 1);
    float sz = __shfl_sync(F, aval, gbl + 2);

    // broadcast A rows (lanes gbl+0..3) to the whole group
    float4 A0, A1, A2, A3;
    A0.x = __shfl_sync(F, acc.x, gbl + 0); A0.y = __shfl_sync(F, acc.y, gbl + 0);
    A0.z = __shfl_sync(F, acc.z, gbl + 0); A0.w = __shfl_sync(F, acc.w, gbl + 0);
    A1.x = __shfl_sync(F, acc.x, gbl + 1); A1.y = __shfl_sync(F, acc.y, gbl + 1);
    A1.z = __shfl_sync(F, acc.z, gbl + 1); A1.w = __shfl_sync(F, acc.w, gbl + 1);
    A2.x = __shfl_sync(F, acc.x, gbl + 2); A2.y = __shfl_sync(F, acc.y, gbl + 2);
    A2.z = __shfl_sync(F, acc.z, gbl + 2); A2.w = __shfl_sync(F, acc.w, gbl + 2);
    A3.x = __shfl_sync(F, acc.x, gbl + 3); A3.y = __shfl_sync(F, acc.y, gbl + 3);
    A3.z = __shfl_sync(F, acc.z, gbl + 3); A3.w = __shfl_sync(F, acc.w, gbl + 3);

    if (n < N && k >= 4) {
        const int i = k - 4;                   // C row index
        float4 R;                              // R row i = C_i @ A
        R.x = acc.x * A0.x + acc.y * A1.x + acc.z * A2.x + acc.w * A3.x;
        R.y = acc.x * A0.y + acc.y * A1.y + acc.z * A2.y + acc.w * A3.y;
        R.z = acc.x * A0.z + acc.y * A1.z + acc.z * A2.z + acc.w * A3.z;
        R.w = acc.x * A0.w + acc.y * A1.w + acc.z * A2.w + acc.w * A3.w;
        ((float4*)out_w)[idx * 4 + i] = R;
        if (i < 3)
            out_xd[idx * 3 + i] = acc.x * sx + acc.y * sy + acc.z * sz + acc.w;
    }
}

// ---------------------------------------------------------------------------
// Host: resolve inputs by exact element count (ordering-independent binding).
// ---------------------------------------------------------------------------
extern "C" void kernel_launch(void* const* d_in, const int* in_sizes, int n_in,
                              void* d_out, int out_size) {
    const float *tfs = nullptr, *tfs_inv = nullptr, *poseoff_ori = nullptr,
                *lbsw = nullptr, *vol = nullptr;
    const void  *mask = nullptr;
    const float *p3M[3] = {nullptr, nullptr, nullptr};
    const float *psm[2] = {nullptr, nullptr};
    int c3 = 0, cs = 0;
    int idx_mask = -1, idx_first3M = -1;

    for (int i = 0; i < n_in; i++) {
        switch (in_sizes[i]) {
            case 3520:     tfs = (const float*)d_in[i]; break;
            case 880:      tfs_inv = (const float*)d_in[i]; break;
            case 750000:   poseoff_ori = (const float*)d_in[i]; break;
            case 13750000: lbsw = (const float*)d_in[i]; break;
            case 250000:   mask = d_in[i]; idx_mask = i; break;
            case 3604480:  vol = (const float*)d_in[i]; break;
            case 3:        if (cs < 2) psm[cs++] = (const float*)d_in[i]; break;
            case 3000000:
                if (c3 == 0) idx_first3M = i;
                if (c3 < 3) p3M[c3++] = (const float*)d_in[i];
                break;
            default: break;
        }
    }

    const int N = 250000, B = 4;

    const float* xc        = (idx_mask >= 0 && idx_first3M >= 0 && idx_mask < idx_first3M)
                             ? p3M[2] : p3M[0];
    const float* shape_off = (xc == p3M[0]) ? p3M[1] : p3M[0];
    const float* pose_off  = (xc == p3M[0]) ? p3M[2] : p3M[1];
    const float* offk = psm[0];
    const float* sclk = psm[1];

    float* out_xd = (float*)d_out;
    float* out_w  = out_xd + (size_t)B * N * 3;

    reset_flag_kernel<<<1, 1>>>();
    detect_mask_kernel<<<(65536 + 255) / 256, 256>>>((const unsigned char*)mask, N);
    compact_mask_kernel<<<(N + 255) / 256, 256>>>(mask, N);

    dim3 g1(NVOX / 512, 5);
    preblend_vox_kernel<<<g1, 256>>>(vol, tfs, tfs_inv);

    dim3 b2(32, 5);
    preblend_pts_kernel<<<(N + 63) / 64, b2>>>(lbsw, tfs, tfs_inv);

    dim3 g3((N + 31) / 32, 4);
    deform_kernel<<<g3, 256>>>(xc, shape_off, pose_off, poseoff_ori, mask,
                               offk, sclk, out_xd, out_w, N);
}